// round 7
// baseline (speedup 1.0000x reference)
#include <cuda_runtime.h>
#include <math.h>

// ---------------- problem constants ----------------
#define T_STEPS 512
#define BATCH   128
#define HDIM    300
#define MCELLS  20
#define ROWS    (BATCH*MCELLS)   // 2560
#define DECAY   0.98f
#define EPS_V   1e-8f

#define NTHREADS 256
#define NJOBS    1260  // (3 matrices * 20rt*5ct + P 1rt*15ct) * 4 K-quarters
#define RH       (ROWS*HDIM)
#define PSZ      (BATCH*900)

// 1 = JAX >= 0.4.30 default (threefry_partitionable)
#define THREEFRY_PARTITIONABLE 1

// ---------------- device state (no allocation anywhere) ----------------
__device__ float g_mem[RH];            // (B,M,H)
__device__ float g_usage[ROWS];        // (B,M)
__device__ float g_HP [4*RH];          // mem@Ws1[0:300]      per K-quarter
__device__ float g_HP2[4*RH];          // (h*mem)@Ws1[600:900] per K-quarter
__device__ float g_CP [4*RH];          // mem@Wu[300:600]      per K-quarter
__device__ float g_P  [4*PSZ];         // h@[We1|Ws1(300:600)|Wu(0:300)] per K-quarter
__device__ float g_cand[RH];           // tanh(ΣCP + P6 + bu)
__device__ float g_ow[ROWS];           // gating outputs for phase C
__device__ float g_indv[ROWS];
__device__ unsigned g_count;           // grid-barrier counter
__device__ unsigned g_jobctr[T_STEPS]; // per-step dynamic job counters

// ---------------- software grid barrier ----------------
__device__ __forceinline__ void grid_bar(unsigned &target, int nblk) {
    __syncthreads();
    if (threadIdx.x == 0) {
        target += (unsigned)nblk;
        __threadfence();
        atomicAdd(&g_count, 1u);
        volatile unsigned* p = &g_count;
        while (*p < target) { }
        __threadfence();
    }
    __syncthreads();
}

// ---------------- JAX threefry-2x32-20 noise ----------------
__device__ __forceinline__ void tf_round(unsigned &x0, unsigned &x1, int r) {
    x0 += x1;
    x1 = (x1 << r) | (x1 >> (32 - r));
    x1 ^= x0;
}
__device__ __forceinline__ void threefry2x32(unsigned c0, unsigned c1,
                                             unsigned &o0, unsigned &o1) {
    const unsigned k0 = 0u, k1 = 42u, k2 = 0x1BD11BDAu ^ 0u ^ 42u;
    unsigned x0 = c0 + k0, x1 = c1 + k1;
    tf_round(x0,x1,13); tf_round(x0,x1,15); tf_round(x0,x1,26); tf_round(x0,x1,6);
    x0 += k1; x1 += k2 + 1u;
    tf_round(x0,x1,17); tf_round(x0,x1,29); tf_round(x0,x1,16); tf_round(x0,x1,24);
    x0 += k2; x1 += k0 + 2u;
    tf_round(x0,x1,13); tf_round(x0,x1,15); tf_round(x0,x1,26); tf_round(x0,x1,6);
    x0 += k0; x1 += k1 + 3u;
    tf_round(x0,x1,17); tf_round(x0,x1,29); tf_round(x0,x1,16); tf_round(x0,x1,24);
    x0 += k1; x1 += k2 + 4u;
    tf_round(x0,x1,13); tf_round(x0,x1,15); tf_round(x0,x1,26); tf_round(x0,x1,6);
    x0 += k2; x1 += k0 + 5u;
    o0 = x0; o1 = x1;
}
__device__ __forceinline__ float jax_noise(unsigned i) {
    unsigned bits;
#if THREEFRY_PARTITIONABLE
    unsigned o0, o1;
    threefry2x32(0u, i, o0, o1);
    bits = o0 ^ o1;
#else
    const unsigned half = (unsigned)(T_STEPS*BATCH*MCELLS) / 2u;
    unsigned o0, o1;
    if (i < half) { threefry2x32(i, i + half, o0, o1); bits = o0; }
    else          { threefry2x32(i - half, i, o0, o1); bits = o1; }
#endif
    float f = __uint_as_float((bits >> 9) | 0x3f800000u) - 1.0f;
    float u = __fadd_rn(__fmul_rn(f, 0.99f), 0.01f);
    return fmaxf(0.01f, u);
}

// ---------------- warp reductions ----------------
__device__ __forceinline__ float warpSum(float v) {
#pragma unroll
    for (int o = 16; o; o >>= 1) v += __shfl_xor_sync(0xffffffffu, v, o);
    return v;
}
__device__ __forceinline__ float warpMax(float v) {
#pragma unroll
    for (int o = 16; o; o >>= 1) v = fmaxf(v, __shfl_xor_sync(0xffffffffu, v, o));
    return v;
}

// fast tanh: abs err ~1e-6; __expf(inf)->inf gives exact saturation
__device__ __forceinline__ float tanh_fast(float x) {
    float ax = fabsf(x);
    float e  = __expf(2.0f * ax);
    float r  = 1.0f - __fdividef(2.0f, e + 1.0f);
    return copysignf(r, x);
}

// ---------------- GEMM tile job ----------------
// 1260 jobs. job<1200: mtype=job/400 (0=HP 1=HP2 2=CP), e=job%400, kq=e&3,
//   e2=e>>2: r0=(e2/5)*128 (2560 rows), c0=(e2%5)*64 (300 cols).
// job>=1200: P: e=job-1200, kq=e&3, ct=e>>2 (15 col tiles over 900), r0=0.
// K-quarter: kstart=kq*80; ntiles = kq<3 ? 4 : 3 (BK=20).
#define BM 128
#define BN 64
#define BK 20

__device__ __forceinline__ void gemm_job(
    int job, int t,
    const float* __restrict__ hs, const float* __restrict__ We1,
    const float* __restrict__ Ws1, const float* __restrict__ Wu,
    float (&As)[2][BK][BM+4], float (&Bs)[2][BK][BN])
{
    const int tid = threadIdx.x;
    const float* hbase = hs + (size_t)t * BATCH * HDIM;

    int mtype, r0, c0, kq, ncols;
    if (job < 1200) {
        mtype = job / 400;
        int e = job % 400;  kq = e & 3;  int e2 = e >> 2;
        r0 = (e2 / 5) * BM;  c0 = (e2 % 5) * BN;  ncols = 300;
    } else {
        mtype = 3;
        int e = job - 1200; kq = e & 3;
        r0 = 0;  c0 = (e >> 2) * BN;  ncols = 900;
    }
    const int kstart = kq * 80;
    const int ntiles = (kq < 3) ? 4 : 3;

    const int tx = tid & 15;           // 16 col groups of 4
    const int ty = tid >> 4;           // 16 row groups of 8
    float acc[8][4];
#pragma unroll
    for (int i = 0; i < 8; i++)
#pragma unroll
        for (int j = 0; j < 4; j++) acc[i][j] = 0.f;

    float ra[10], rb[5];

    auto loadA = [&](int kt) {
#pragma unroll
        for (int i = 0; i < 10; i++) {
            int idx = tid + i*NTHREADS;
            int r = idx / BK, k = idx - (idx / BK) * BK;
            int rg = r0 + r, kg = kstart + kt*BK + k;
            float v;
            if (mtype == 0 || mtype == 2) v = g_mem[rg*HDIM + kg];
            else if (mtype == 1)          v = g_mem[rg*HDIM + kg] *
                                              hbase[(rg/MCELLS)*HDIM + kg];
            else                          v = hbase[rg*HDIM + kg];
            ra[i] = v;
        }
    };
    auto loadB = [&](int kt) {
#pragma unroll
        for (int i = 0; i < 5; i++) {
            int idx = tid + i*NTHREADS;
            int k = idx >> 6, j = idx & 63;
            int kg = kstart + kt*BK + k, jg = c0 + j;
            float v = 0.f;
            if (jg < ncols) {
                if (mtype == 0)      v = Ws1[kg*300 + jg];
                else if (mtype == 1) v = Ws1[(kg + 600)*300 + jg];
                else if (mtype == 2) v = Wu[(kg + 300)*300 + jg];
                else {
                    int role = jg / 300, jc = jg - role*300;
                    if (role == 0)      v = We1[kg*300 + jc];
                    else if (role == 1) v = Ws1[(kg + 300)*300 + jc];
                    else                v = Wu[kg*300 + jc];
                }
            }
            rb[i] = v;
        }
    };
    auto storeTiles = [&](int buf) {
#pragma unroll
        for (int i = 0; i < 10; i++) {
            int idx = tid + i*NTHREADS;
            int r = idx / BK, k = idx - (idx / BK) * BK;
            As[buf][k][r] = ra[i];
        }
#pragma unroll
        for (int i = 0; i < 5; i++) {
            int idx = tid + i*NTHREADS;
            int k = idx >> 6, j = idx & 63;
            Bs[buf][k][j] = rb[i];
        }
    };

    loadA(0); loadB(0);
    storeTiles(0);
    __syncthreads();

    for (int kt = 0; kt < ntiles; kt++) {
        int cur = kt & 1;
        if (kt + 1 < ntiles) { loadA(kt + 1); loadB(kt + 1); }
#pragma unroll
        for (int k = 0; k < BK; k++) {
            float4 a0 = *(const float4*)&As[cur][k][ty*8];
            float4 a1 = *(const float4*)&As[cur][k][ty*8 + 4];
            float4 bv = *(const float4*)&Bs[cur][k][tx*4];
            acc[0][0] = fmaf(a0.x, bv.x, acc[0][0]); acc[0][1] = fmaf(a0.x, bv.y, acc[0][1]);
            acc[0][2] = fmaf(a0.x, bv.z, acc[0][2]); acc[0][3] = fmaf(a0.x, bv.w, acc[0][3]);
            acc[1][0] = fmaf(a0.y, bv.x, acc[1][0]); acc[1][1] = fmaf(a0.y, bv.y, acc[1][1]);
            acc[1][2] = fmaf(a0.y, bv.z, acc[1][2]); acc[1][3] = fmaf(a0.y, bv.w, acc[1][3]);
            acc[2][0] = fmaf(a0.z, bv.x, acc[2][0]); acc[2][1] = fmaf(a0.z, bv.y, acc[2][1]);
            acc[2][2] = fmaf(a0.z, bv.z, acc[2][2]); acc[2][3] = fmaf(a0.z, bv.w, acc[2][3]);
            acc[3][0] = fmaf(a0.w, bv.x, acc[3][0]); acc[3][1] = fmaf(a0.w, bv.y, acc[3][1]);
            acc[3][2] = fmaf(a0.w, bv.z, acc[3][2]); acc[3][3] = fmaf(a0.w, bv.w, acc[3][3]);
            acc[4][0] = fmaf(a1.x, bv.x, acc[4][0]); acc[4][1] = fmaf(a1.x, bv.y, acc[4][1]);
            acc[4][2] = fmaf(a1.x, bv.z, acc[4][2]); acc[4][3] = fmaf(a1.x, bv.w, acc[4][3]);
            acc[5][0] = fmaf(a1.y, bv.x, acc[5][0]); acc[5][1] = fmaf(a1.y, bv.y, acc[5][1]);
            acc[5][2] = fmaf(a1.y, bv.z, acc[5][2]); acc[5][3] = fmaf(a1.y, bv.w, acc[5][3]);
            acc[6][0] = fmaf(a1.z, bv.x, acc[6][0]); acc[6][1] = fmaf(a1.z, bv.y, acc[6][1]);
            acc[6][2] = fmaf(a1.z, bv.z, acc[6][2]); acc[6][3] = fmaf(a1.z, bv.w, acc[6][3]);
            acc[7][0] = fmaf(a1.w, bv.x, acc[7][0]); acc[7][1] = fmaf(a1.w, bv.y, acc[7][1]);
            acc[7][2] = fmaf(a1.w, bv.z, acc[7][2]); acc[7][3] = fmaf(a1.w, bv.w, acc[7][3]);
        }
        if (kt + 1 < ntiles) storeTiles(cur ^ 1);
        __syncthreads();
    }

    float* dst;
    if (mtype == 0)      dst = g_HP  + kq*RH;
    else if (mtype == 1) dst = g_HP2 + kq*RH;
    else if (mtype == 2) dst = g_CP  + kq*RH;
    else                 dst = g_P   + kq*PSZ;
#pragma unroll
    for (int i = 0; i < 8; i++) {
        int rg = r0 + ty*8 + i;
#pragma unroll
        for (int j = 0; j < 4; j++) {
            int jg = c0 + tx*4 + j;
            if (jg < ncols) dst[rg*ncols + jg] = acc[i][j];
        }
    }
}

// ---------------- gating job (block handles batch b) ----------------
__device__ __forceinline__ void gate_job(
    int b, int t,
    const float* __restrict__ mask,
    const float* __restrict__ be1, const float* __restrict__ We2,
    const float* __restrict__ be2, const float* __restrict__ bs1,
    const float* __restrict__ Ws2, const float* __restrict__ bs2,
    const float* __restrict__ Ws1,
    float* __restrict__ out,
    float (&s_sim)[MCELLS], float (&s_usage)[MCELLS],
    float (&s_red)[8], float &s_ent)
{
    const int tid = threadIdx.x;
    const int warp = tid >> 5, lane = tid & 31;

    const float* P0 = g_P + b*900;
    const float* P1 = g_P + PSZ   + b*900;
    const float* P2 = g_P + 2*PSZ + b*900;
    const float* P3 = g_P + 3*PSZ + b*900;
    const float* wu_row = Ws1 + 900*300;

    if (tid < MCELLS) s_usage[tid] = g_usage[b*MCELLS + tid];
    __syncthreads();

    // ---- entity prob ----
    float acc = 0.f;
    for (int j = tid; j < 300; j += NTHREADS)
        acc += fmaxf(P0[j] + P1[j] + P2[j] + P3[j] + be1[j], 0.f) * We2[j];
    acc = warpSum(acc);
    if (lane == 0) s_red[warp] = acc;
    __syncthreads();
    if (tid == 0) {
        float s = 0.f;
        for (int w = 0; w < 8; w++) s += s_red[w];
        float score = s + be2[0];
        float sig = 1.f / (1.f + expf(-score));
        s_ent = sig * mask[(size_t)t*BATCH + b];
    }

    // ---- sim[m] ----
    for (int m = warp; m < MCELLS; m += 8) {
        float u = s_usage[m];
        const int ro = (b*MCELLS + m)*300;
        float a = 0.f;
        for (int j = lane; j < 300; j += 32) {
            float hp  = g_HP [ro+j] + g_HP [RH+ro+j] + g_HP [2*RH+ro+j] + g_HP [3*RH+ro+j];
            float hp2 = g_HP2[ro+j] + g_HP2[RH+ro+j] + g_HP2[2*RH+ro+j] + g_HP2[3*RH+ro+j];
            float ph  = P0[300+j] + P1[300+j] + P2[300+j] + P3[300+j];
            float pre = hp + hp2 + ph + u*wu_row[j] + bs1[j];
            a += fmaxf(pre, 0.f) * Ws2[j];
        }
        a = warpSum(a);
        if (lane == 0) s_sim[m] = a + bs2[0];
    }
    __syncthreads();

    // ---- gating (warp 0; lane = slot 0..20) ----
    if (warp == 0) {
        const unsigned FULL = 0xffffffffu;
        const int m = lane;
        const float NEG_INF = -INFINITY;
        float usg  = (m < MCELLS) ? s_usage[m] : 0.f;
        float simv = (m < MCELLS) ? s_sim[m]   : 0.f;

        float comb;
        if (m < MCELLS)       comb = (usg > 0.f) ? simv : -10000.f;
        else if (m == MCELLS) comb = 0.f;
        else                  comb = NEG_INF;
        float mx   = warpMax(comb);
        float ex   = (m <= MCELLS) ? expf(comb - mx) : 0.f;
        float esum = warpSum(ex);
        float prob = ex / esum;
        float mult = (m < MCELLS) ? ((usg > 0.f) ? 1.f : 0.f)
                                  : ((m == MCELLS) ? 1.f : 0.f);
        float maskedp = prob * mult;
        float msum = warpSum(maskedp);
        float nrm  = maskedp / (msum + EPS_V);
        float co   = s_ent * nrm;
        float ow_base = __shfl_sync(FULL, co, MCELLS);
        float indv = (m < MCELLS) ? co : 0.f;

        float s2  = (m < MCELLS) ? simv : NEG_INF;
        float mx2 = warpMax(s2);
        float e2  = (m < MCELLS) ? expf(simv - mx2) : 0.f;
        float es2 = warpSum(e2);
        float nsim = e2 / es2;

        float ow_score = (m < MCELLS)
            ? ((usg == 0.f ? nsim * 100000.f : 0.f) + (1.f - usg))
            : NEG_INF;
        float maxv = warpMax(ow_score);
        float nz   = (m < MCELLS && ow_score == maxv)
            ? jax_noise((unsigned)(((size_t)t*BATCH + b)*MCELLS + m)) : 0.f;
        float nzmax = warpMax(nz);
        unsigned ballot = __ballot_sync(FULL, (m < MCELLS) && (nz == nzmax));
        int idx = __ffs(ballot) - 1;

        float ow = (m == idx) ? ow_base : 0.f;
        float nu = fminf(1.f, ow + indv + DECAY * usg);

        float* out_ent = out;
        float* out_usg = out + (size_t)T_STEPS*BATCH;
        float* out_crf = out_usg + (size_t)T_STEPS*BATCH*MCELLS;
        float* out_ow  = out_crf + (size_t)T_STEPS*BATCH*MCELLS;
        if (m < MCELLS) {
            g_ow[b*MCELLS + m]    = ow;
            g_indv[b*MCELLS + m]  = indv;
            g_usage[b*MCELLS + m] = nu;
            size_t o = ((size_t)t*BATCH + b)*MCELLS + m;
            out_usg[o] = nu;
            out_crf[o] = indv * (1.f - EPS_V) + EPS_V;
            out_ow[o]  = ow   * (1.f - EPS_V) + EPS_V;
        }
        if (m == 0)
            out_ent[(size_t)t*BATCH + b] = s_ent * (1.f - EPS_V) + EPS_V;
    }
}

// ---------------- persistent kernel ----------------
__global__ __launch_bounds__(NTHREADS, 2) void k_persist(
    const float* __restrict__ hs, const float* __restrict__ mask,
    const float* __restrict__ We1, const float* __restrict__ be1,
    const float* __restrict__ We2, const float* __restrict__ be2,
    const float* __restrict__ Ws1, const float* __restrict__ bs1,
    const float* __restrict__ Ws2, const float* __restrict__ bs2,
    const float* __restrict__ Wu,  const float* __restrict__ bu,
    float* __restrict__ out, int nblk)
{
    __shared__ float As[2][BK][BM+4];
    __shared__ float Bs[2][BK][BN];
    __shared__ float s_sim[MCELLS], s_usage[MCELLS];
    __shared__ float s_red[8];
    __shared__ float s_ent;
    __shared__ int s_job;

    const int tid = threadIdx.x;
    unsigned target = 0;

    for (int t = 0; t < T_STEPS; t++) {
        // ---- phase A: GEMMs (dynamic) ----
        for (;;) {
            if (tid == 0) s_job = (int)atomicAdd(&g_jobctr[t], 1u);
            __syncthreads();
            int job = s_job;
            __syncthreads();
            if (job >= NJOBS) break;
            gemm_job(job, t, hs, We1, Ws1, Wu, As, Bs);
        }
        grid_bar(target, nblk);

        // ---- phase B: gate (blocks 0..127) || cand precompute (rest) ----
        if (blockIdx.x < BATCH) {
            gate_job(blockIdx.x, t, mask, be1, We2, be2, bs1, Ws2, bs2,
                     Ws1, out, s_sim, s_usage, s_red, s_ent);
        } else {
            const float4* CP0 = (const float4*)g_CP;
            const float4* CP1 = (const float4*)(g_CP + RH);
            const float4* CP2 = (const float4*)(g_CP + 2*RH);
            const float4* CP3 = (const float4*)(g_CP + 3*RH);
            const float4* bu4 = (const float4*)bu;
            float4* cand4 = (float4*)g_cand;
            const int total = ROWS * 75;
            const int nb = nblk - BATCH;
            for (int idx = (blockIdx.x - BATCH)*NTHREADS + tid; idx < total;
                 idx += nb*NTHREADS) {
                int r  = idx / 75;
                int jq = idx - r*75;
                int b  = r / MCELLS;
                float4 c0 = CP0[idx], c1 = CP1[idx], c2 = CP2[idx], c3 = CP3[idx];
                float4 bv = bu4[jq];
                float4 res;
                int pbase = b*225 + 150 + jq;
                float4 p0 = ((const float4*)g_P)[pbase];
                float4 p1 = ((const float4*)(g_P + PSZ))[pbase];
                float4 p2 = ((const float4*)(g_P + 2*PSZ))[pbase];
                float4 p3 = ((const float4*)(g_P + 3*PSZ))[pbase];
                res.x = tanh_fast(c0.x+c1.x+c2.x+c3.x + p0.x+p1.x+p2.x+p3.x + bv.x);
                res.y = tanh_fast(c0.y+c1.y+c2.y+c3.y + p0.y+p1.y+p2.y+p3.y + bv.y);
                res.z = tanh_fast(c0.z+c1.z+c2.z+c3.z + p0.z+p1.z+p2.z+p3.z + bv.z);
                res.w = tanh_fast(c0.w+c1.w+c2.w+c3.w + p0.w+p1.w+p2.w+p3.w + bv.w);
                cand4[idx] = res;
            }
        }
        grid_bar(target, nblk);

        // ---- phase C: mem update (all blocks, float4) ----
        {
            const float4* hb4 = (const float4*)(hs + (size_t)t*BATCH*HDIM);
            const float4* cand4 = (const float4*)g_cand;
            float4* mem4 = (float4*)g_mem;
            const int total = ROWS * 75;
            for (int idx = blockIdx.x*NTHREADS + tid; idx < total;
                 idx += nblk*NTHREADS) {
                int r  = idx / 75;
                int jq = idx - r*75;
                int b  = r / MCELLS;
                float owv = g_ow[r], iv = g_indv[r];
                float coef = 1.f - owv - iv;
                float4 cd = cand4[idx];
                float4 h  = hb4[b*75 + jq];
                float4 mo = mem4[idx];
                float4 res;
                res.x = owv*h.x + coef*mo.x + iv*cd.x;
                res.y = owv*h.y + coef*mo.y + iv*cd.y;
                res.z = owv*h.z + coef*mo.z + iv*cd.z;
                res.w = owv*h.w + coef*mo.w + iv*cd.w;
                mem4[idx] = res;
            }
        }
        grid_bar(target, nblk);
    }
}

extern "C" void kernel_launch(void* const* d_in, const int* in_sizes, int n_in,
                              void* d_out, int out_size) {
    const float* hs   = (const float*)d_in[0];
    const float* mask = (const float*)d_in[1];
    const float* We1  = (const float*)d_in[2];
    const float* be1  = (const float*)d_in[3];
    const float* We2  = (const float*)d_in[4];
    const float* be2  = (const float*)d_in[5];
    const float* Ws1  = (const float*)d_in[6];
    const float* bs1  = (const float*)d_in[7];
    const float* Ws2  = (const float*)d_in[8];
    const float* bs2  = (const float*)d_in[9];
    const float* Wu   = (const float*)d_in[10];
    const float* bu   = (const float*)d_in[11];
    float* out = (float*)d_out;

    int smcount = 148;
    cudaDeviceGetAttribute(&smcount, cudaDevAttrMultiProcessorCount, 0);
    int nblk = 2 * smcount;

    void *pmem, *pusg, *pcnt, *pjob;
    cudaGetSymbolAddress(&pmem, g_mem);
    cudaGetSymbolAddress(&pusg, g_usage);
    cudaGetSymbolAddress(&pcnt, g_count);
    cudaGetSymbolAddress(&pjob, g_jobctr);
    cudaMemsetAsync(pmem, 0, sizeof(float)*(size_t)RH);
    cudaMemsetAsync(pusg, 0, sizeof(float)*(size_t)ROWS);
    cudaMemsetAsync(pcnt, 0, sizeof(unsigned));
    cudaMemsetAsync(pjob, 0, sizeof(unsigned)*T_STEPS);

    k_persist<<<nblk, NTHREADS>>>(hs, mask, We1, be1, We2, be2,
                                  Ws1, bs1, Ws2, bs2, Wu, bu, out, nblk);
}

// round 8
// speedup vs baseline: 1.1519x; 1.1519x over previous
#include <cuda_runtime.h>
#include <math.h>

// ---------------- problem constants ----------------
#define T_STEPS 512
#define BATCH   128
#define HDIM    300
#define MCELLS  20
#define ROWS    (BATCH*MCELLS)   // 2560
#define DECAY   0.98f
#define EPS_V   1e-8f

#define NTHREADS 256
#define NJOBS    1260  // (3 matrices * 40rt*5ct + P 2rt*15ct) * 2 K-halves
#define RH       (ROWS*HDIM)
#define PSZ      (BATCH*900)

// 1 = JAX >= 0.4.30 default (threefry_partitionable)
#define THREEFRY_PARTITIONABLE 1

// ---------------- device state (no allocation anywhere) ----------------
__device__ float g_mem[RH];             // (B,M,H)
__device__ float g_usage[ROWS];         // (B,M)
__device__ float g_HPa [RH];            // mem@Ws1[0:300], K half 0
__device__ float g_HPb [RH];            // K half 1
__device__ float g_HP2a[RH];            // (h*mem)@Ws1[600:900] halves
__device__ float g_HP2b[RH];
__device__ float g_CPa [RH];            // mem@Wu[300:600] halves
__device__ float g_CPb [RH];
__device__ float g_Pa[PSZ];             // h@[We1|Ws1(300:600)|Wu(0:300)] halves
__device__ float g_Pb[PSZ];
__device__ float g_cand[RH];            // tanh(CPa+CPb + P6 + bu)
__device__ float g_ow[ROWS];
__device__ float g_indv[ROWS];
__device__ unsigned g_count;            // grid-barrier counter
__device__ unsigned g_jobctr[T_STEPS];  // per-step dynamic job counters

// ---------------- software grid barrier ----------------
__device__ __forceinline__ void grid_bar(unsigned &target, int nblk) {
    __syncthreads();
    if (threadIdx.x == 0) {
        target += (unsigned)nblk;
        __threadfence();
        atomicAdd(&g_count, 1u);
        volatile unsigned* p = &g_count;
        while (*p < target) { }
        __threadfence();
    }
    __syncthreads();
}

// ---------------- JAX threefry-2x32-20 noise ----------------
__device__ __forceinline__ void tf_round(unsigned &x0, unsigned &x1, int r) {
    x0 += x1;
    x1 = (x1 << r) | (x1 >> (32 - r));
    x1 ^= x0;
}
__device__ __forceinline__ void threefry2x32(unsigned c0, unsigned c1,
                                             unsigned &o0, unsigned &o1) {
    const unsigned k0 = 0u, k1 = 42u, k2 = 0x1BD11BDAu ^ 0u ^ 42u;
    unsigned x0 = c0 + k0, x1 = c1 + k1;
    tf_round(x0,x1,13); tf_round(x0,x1,15); tf_round(x0,x1,26); tf_round(x0,x1,6);
    x0 += k1; x1 += k2 + 1u;
    tf_round(x0,x1,17); tf_round(x0,x1,29); tf_round(x0,x1,16); tf_round(x0,x1,24);
    x0 += k2; x1 += k0 + 2u;
    tf_round(x0,x1,13); tf_round(x0,x1,15); tf_round(x0,x1,26); tf_round(x0,x1,6);
    x0 += k0; x1 += k1 + 3u;
    tf_round(x0,x1,17); tf_round(x0,x1,29); tf_round(x0,x1,16); tf_round(x0,x1,24);
    x0 += k1; x1 += k2 + 4u;
    tf_round(x0,x1,13); tf_round(x0,x1,15); tf_round(x0,x1,26); tf_round(x0,x1,6);
    x0 += k2; x1 += k0 + 5u;
    o0 = x0; o1 = x1;
}
__device__ __forceinline__ float jax_noise(unsigned i) {
    unsigned bits;
#if THREEFRY_PARTITIONABLE
    unsigned o0, o1;
    threefry2x32(0u, i, o0, o1);
    bits = o0 ^ o1;
#else
    const unsigned half = (unsigned)(T_STEPS*BATCH*MCELLS) / 2u;
    unsigned o0, o1;
    if (i < half) { threefry2x32(i, i + half, o0, o1); bits = o0; }
    else          { threefry2x32(i - half, i, o0, o1); bits = o1; }
#endif
    float f = __uint_as_float((bits >> 9) | 0x3f800000u) - 1.0f;
    float u = __fadd_rn(__fmul_rn(f, 0.99f), 0.01f);
    return fmaxf(0.01f, u);
}

// ---------------- warp reductions ----------------
__device__ __forceinline__ float warpSum(float v) {
#pragma unroll
    for (int o = 16; o; o >>= 1) v += __shfl_xor_sync(0xffffffffu, v, o);
    return v;
}
__device__ __forceinline__ float warpMax(float v) {
#pragma unroll
    for (int o = 16; o; o >>= 1) v = fmaxf(v, __shfl_xor_sync(0xffffffffu, v, o));
    return v;
}

// fast tanh: abs err ~1e-6; __expf(inf)->inf gives exact saturation
__device__ __forceinline__ float tanh_fast(float x) {
    float ax = fabsf(x);
    float e  = __expf(2.0f * ax);
    float r  = 1.0f - __fdividef(2.0f, e + 1.0f);
    return copysignf(r, x);
}

// ---------------- GEMM tile job ----------------
// 1260 jobs. job<1200: mtype=job/400 (0=HP 1=HP2 2=CP), e=job%400, kh=e&1,
//   e2=e>>1: r0=(e2/5)*64 (2560 rows), c0=(e2%5)*64 (300 cols).
// job>=1200: P: e=job-1200, kh=e&1, e2=e>>1: r0=(e2/15)*64 (128 rows),
//   c0=(e2%15)*64 (900 cols).
// K-half: kh=0 -> K[0,140) 7 tiles; kh=1 -> K[140,300) 8 tiles.
#define BM 64
#define BN 64
#define BK 20

__device__ __forceinline__ void gemm_job(
    int job, int t,
    const float* __restrict__ hs, const float* __restrict__ We1,
    const float* __restrict__ Ws1, const float* __restrict__ Wu,
    float (&As)[2][BK][BM+4], float (&Bs)[2][BK][BN])
{
    const int tid = threadIdx.x;
    const float* hbase = hs + (size_t)t * BATCH * HDIM;

    int mtype, r0, c0, kh, ncols;
    if (job < 1200) {
        mtype = job / 400;
        int e = job % 400;  kh = e & 1;  int e2 = e >> 1;
        r0 = (e2 / 5) * BM;  c0 = (e2 % 5) * BN;  ncols = 300;
    } else {
        mtype = 3;
        int e = job - 1200; kh = e & 1;  int e2 = e >> 1;
        r0 = (e2 / 15) * BM; c0 = (e2 % 15) * BN; ncols = 900;
    }
    const int kstart = kh ? 140 : 0;
    const int ntiles = kh ? 8 : 7;

    // ---- hoisted per-thread tile coordinates (loop-invariant) ----
    int aR[5], aK[5];                   // A: idx -> (row, k)
    const float* aBase[5];              // source row base (already includes row*300)
    const float* aHrow[5];              // h row base for mtype==1
#pragma unroll
    for (int i = 0; i < 5; i++) {
        int idx = tid + i*NTHREADS;
        aR[i] = idx / BK;
        aK[i] = idx - aR[i]*BK;
        int rg = r0 + aR[i];
        const float* src = (mtype == 3) ? hbase : g_mem;
        aBase[i] = src + rg*HDIM;
        aHrow[i] = hbase + (rg/MCELLS)*HDIM;
    }
    int bK[5], bJ[5];                   // B: idx -> (k, col)
    const float* bBase[5];              // base such that value = bBase[i][kg*300]
    bool bOK[5];
#pragma unroll
    for (int i = 0; i < 5; i++) {
        int idx = tid + i*NTHREADS;
        bK[i] = idx >> 6;
        bJ[i] = idx & 63;
        int jg = c0 + bJ[i];
        bOK[i] = (jg < ncols);
        const float* bp;
        if (mtype == 0)      bp = Ws1 + jg;
        else if (mtype == 1) bp = Ws1 + 600*300 + jg;
        else if (mtype == 2) bp = Wu  + 300*300 + jg;
        else {
            int role = jg / 300, jc = jg - role*300;
            if (role == 0)      bp = We1 + jc;
            else if (role == 1) bp = Ws1 + 300*300 + jc;
            else                bp = Wu  + jc;
        }
        bBase[i] = bp;
    }

    const int tx = tid & 15;
    const int ty = tid >> 4;
    float acc[4][4];
#pragma unroll
    for (int i = 0; i < 4; i++)
#pragma unroll
        for (int j = 0; j < 4; j++) acc[i][j] = 0.f;

    float ra[5], rb[5];
    auto loadA = [&](int kt) {
        int kb = kstart + kt*BK;
#pragma unroll
        for (int i = 0; i < 5; i++) {
            int kg = kb + aK[i];
            float v = aBase[i][kg];
            if (mtype == 1) v *= aHrow[i][kg];
            ra[i] = v;
        }
    };
    auto loadB = [&](int kt) {
        int kb = kstart + kt*BK;
#pragma unroll
        for (int i = 0; i < 5; i++) {
            int kg = kb + bK[i];
            rb[i] = bOK[i] ? bBase[i][kg*300] : 0.f;
        }
    };
    auto storeTiles = [&](int buf) {
#pragma unroll
        for (int i = 0; i < 5; i++) As[buf][aK[i]][aR[i]] = ra[i];
#pragma unroll
        for (int i = 0; i < 5; i++) Bs[buf][bK[i]][bJ[i]] = rb[i];
    };

    loadA(0); loadB(0);
    storeTiles(0);
    __syncthreads();

    for (int kt = 0; kt < ntiles; kt++) {
        int cur = kt & 1;
        if (kt + 1 < ntiles) { loadA(kt + 1); loadB(kt + 1); }
#pragma unroll
        for (int k = 0; k < BK; k++) {
            float4 av = *(const float4*)&As[cur][k][ty*4];
            float4 bv = *(const float4*)&Bs[cur][k][tx*4];
            acc[0][0] = fmaf(av.x, bv.x, acc[0][0]); acc[0][1] = fmaf(av.x, bv.y, acc[0][1]);
            acc[0][2] = fmaf(av.x, bv.z, acc[0][2]); acc[0][3] = fmaf(av.x, bv.w, acc[0][3]);
            acc[1][0] = fmaf(av.y, bv.x, acc[1][0]); acc[1][1] = fmaf(av.y, bv.y, acc[1][1]);
            acc[1][2] = fmaf(av.y, bv.z, acc[1][2]); acc[1][3] = fmaf(av.y, bv.w, acc[1][3]);
            acc[2][0] = fmaf(av.z, bv.x, acc[2][0]); acc[2][1] = fmaf(av.z, bv.y, acc[2][1]);
            acc[2][2] = fmaf(av.z, bv.z, acc[2][2]); acc[2][3] = fmaf(av.z, bv.w, acc[2][3]);
            acc[3][0] = fmaf(av.w, bv.x, acc[3][0]); acc[3][1] = fmaf(av.w, bv.y, acc[3][1]);
            acc[3][2] = fmaf(av.w, bv.z, acc[3][2]); acc[3][3] = fmaf(av.w, bv.w, acc[3][3]);
        }
        if (kt + 1 < ntiles) storeTiles(cur ^ 1);
        __syncthreads();
    }

    float* dst;
    if (mtype == 0)      dst = kh ? g_HPb  : g_HPa;
    else if (mtype == 1) dst = kh ? g_HP2b : g_HP2a;
    else if (mtype == 2) dst = kh ? g_CPb  : g_CPa;
    else                 dst = kh ? g_Pb   : g_Pa;
#pragma unroll
    for (int i = 0; i < 4; i++) {
        int rg = r0 + ty*4 + i;
#pragma unroll
        for (int j = 0; j < 4; j++) {
            int jg = c0 + tx*4 + j;
            if (jg < ncols) dst[rg*ncols + jg] = acc[i][j];
        }
    }
}

// ---------------- gating job (block handles batch b) ----------------
__device__ __forceinline__ void gate_job(
    int b, int t,
    const float* __restrict__ mask,
    const float* __restrict__ be1, const float* __restrict__ We2,
    const float* __restrict__ be2, const float* __restrict__ bs1,
    const float* __restrict__ Ws2, const float* __restrict__ bs2,
    const float* __restrict__ Ws1,
    float* __restrict__ out,
    float (&s_sim)[MCELLS], float (&s_usage)[MCELLS],
    float (&s_red)[8], float &s_ent)
{
    const int tid = threadIdx.x;
    const int warp = tid >> 5, lane = tid & 31;

    const float* Pa = g_Pa + b*900;
    const float* Pb = g_Pb + b*900;
    const float* wu_row = Ws1 + 900*300;

    if (tid < MCELLS) s_usage[tid] = g_usage[b*MCELLS + tid];
    __syncthreads();

    // ---- entity prob ----
    float acc = 0.f;
    for (int j = tid; j < 300; j += NTHREADS)
        acc += fmaxf(Pa[j] + Pb[j] + be1[j], 0.f) * We2[j];
    acc = warpSum(acc);
    if (lane == 0) s_red[warp] = acc;
    __syncthreads();
    if (tid == 0) {
        float s = 0.f;
        for (int w = 0; w < 8; w++) s += s_red[w];
        float score = s + be2[0];
        float sig = 1.f / (1.f + expf(-score));
        s_ent = sig * mask[(size_t)t*BATCH + b];
    }

    // ---- sim[m] ----
    for (int m = warp; m < MCELLS; m += 8) {
        float u = s_usage[m];
        const int ro = (b*MCELLS + m)*300;
        float a = 0.f;
        for (int j = lane; j < 300; j += 32) {
            float pre = g_HPa[ro+j] + g_HPb[ro+j] + g_HP2a[ro+j] + g_HP2b[ro+j]
                      + Pa[300 + j] + Pb[300 + j] + u*wu_row[j] + bs1[j];
            a += fmaxf(pre, 0.f) * Ws2[j];
        }
        a = warpSum(a);
        if (lane == 0) s_sim[m] = a + bs2[0];
    }
    __syncthreads();

    // ---- gating (warp 0; lane = slot 0..20) ----
    if (warp == 0) {
        const unsigned FULL = 0xffffffffu;
        const int m = lane;
        const float NEG_INF = -INFINITY;
        float usg  = (m < MCELLS) ? s_usage[m] : 0.f;
        float simv = (m < MCELLS) ? s_sim[m]   : 0.f;

        float comb;
        if (m < MCELLS)       comb = (usg > 0.f) ? simv : -10000.f;
        else if (m == MCELLS) comb = 0.f;
        else                  comb = NEG_INF;
        float mx   = warpMax(comb);
        float ex   = (m <= MCELLS) ? expf(comb - mx) : 0.f;
        float esum = warpSum(ex);
        float prob = ex / esum;
        float mult = (m < MCELLS) ? ((usg > 0.f) ? 1.f : 0.f)
                                  : ((m == MCELLS) ? 1.f : 0.f);
        float maskedp = prob * mult;
        float msum = warpSum(maskedp);
        float nrm  = maskedp / (msum + EPS_V);
        float co   = s_ent * nrm;
        float ow_base = __shfl_sync(FULL, co, MCELLS);
        float indv = (m < MCELLS) ? co : 0.f;

        float s2  = (m < MCELLS) ? simv : NEG_INF;
        float mx2 = warpMax(s2);
        float e2  = (m < MCELLS) ? expf(simv - mx2) : 0.f;
        float es2 = warpSum(e2);
        float nsim = e2 / es2;

        float ow_score = (m < MCELLS)
            ? ((usg == 0.f ? nsim * 100000.f : 0.f) + (1.f - usg))
            : NEG_INF;
        float maxv = warpMax(ow_score);
        float nz   = (m < MCELLS && ow_score == maxv)
            ? jax_noise((unsigned)(((size_t)t*BATCH + b)*MCELLS + m)) : 0.f;
        float nzmax = warpMax(nz);
        unsigned ballot = __ballot_sync(FULL, (m < MCELLS) && (nz == nzmax));
        int idx = __ffs(ballot) - 1;

        float ow = (m == idx) ? ow_base : 0.f;
        float nu = fminf(1.f, ow + indv + DECAY * usg);

        float* out_ent = out;
        float* out_usg = out + (size_t)T_STEPS*BATCH;
        float* out_crf = out_usg + (size_t)T_STEPS*BATCH*MCELLS;
        float* out_ow  = out_crf + (size_t)T_STEPS*BATCH*MCELLS;
        if (m < MCELLS) {
            g_ow[b*MCELLS + m]    = ow;
            g_indv[b*MCELLS + m]  = indv;
            g_usage[b*MCELLS + m] = nu;
            size_t o = ((size_t)t*BATCH + b)*MCELLS + m;
            out_usg[o] = nu;
            out_crf[o] = indv * (1.f - EPS_V) + EPS_V;
            out_ow[o]  = ow   * (1.f - EPS_V) + EPS_V;
        }
        if (m == 0)
            out_ent[(size_t)t*BATCH + b] = s_ent * (1.f - EPS_V) + EPS_V;
    }
}

// ---------------- persistent kernel ----------------
__global__ __launch_bounds__(NTHREADS, 2) void k_persist(
    const float* __restrict__ hs, const float* __restrict__ mask,
    const float* __restrict__ We1, const float* __restrict__ be1,
    const float* __restrict__ We2, const float* __restrict__ be2,
    const float* __restrict__ Ws1, const float* __restrict__ bs1,
    const float* __restrict__ Ws2, const float* __restrict__ bs2,
    const float* __restrict__ Wu,  const float* __restrict__ bu,
    float* __restrict__ out, int nblk)
{
    __shared__ float As[2][BK][BM+4];
    __shared__ float Bs[2][BK][BN];
    __shared__ float s_sim[MCELLS], s_usage[MCELLS];
    __shared__ float s_red[8];
    __shared__ float s_ent;
    __shared__ int s_job;

    const int tid = threadIdx.x;
    unsigned target = 0;

    for (int t = 0; t < T_STEPS; t++) {
        // ---- phase A: GEMMs (dynamic) ----
        for (;;) {
            if (tid == 0) s_job = (int)atomicAdd(&g_jobctr[t], 1u);
            __syncthreads();
            int job = s_job;
            __syncthreads();
            if (job >= NJOBS) break;
            gemm_job(job, t, hs, We1, Ws1, Wu, As, Bs);
        }
        grid_bar(target, nblk);

        // ---- phase B: gate (blocks 0..127) || cand precompute (rest) ----
        if (blockIdx.x < BATCH) {
            gate_job(blockIdx.x, t, mask, be1, We2, be2, bs1, Ws2, bs2,
                     Ws1, out, s_sim, s_usage, s_red, s_ent);
        } else {
            const float4* CPa4 = (const float4*)g_CPa;
            const float4* CPb4 = (const float4*)g_CPb;
            const float4* Pa4  = (const float4*)g_Pa;
            const float4* Pb4  = (const float4*)g_Pb;
            const float4* bu4  = (const float4*)bu;
            float4* cand4 = (float4*)g_cand;
            const int total = ROWS * 75;
            const int nb = nblk - BATCH;
            for (int idx = (blockIdx.x - BATCH)*NTHREADS + tid; idx < total;
                 idx += nb*NTHREADS) {
                int r  = idx / 75;
                int jq = idx - r*75;
                int b  = r / MCELLS;
                float4 ca = CPa4[idx], cb = CPb4[idx];
                int pbase = b*225 + 150 + jq;
                float4 pa = Pa4[pbase], pb = Pb4[pbase];
                float4 bv = bu4[jq];
                float4 res;
                res.x = tanh_fast(ca.x + cb.x + pa.x + pb.x + bv.x);
                res.y = tanh_fast(ca.y + cb.y + pa.y + pb.y + bv.y);
                res.z = tanh_fast(ca.z + cb.z + pa.z + pb.z + bv.z);
                res.w = tanh_fast(ca.w + cb.w + pa.w + pb.w + bv.w);
                cand4[idx] = res;
            }
        }
        grid_bar(target, nblk);

        // ---- phase C: mem update (all blocks, float4) ----
        {
            const float4* hb4 = (const float4*)(hs + (size_t)t*BATCH*HDIM);
            const float4* cand4 = (const float4*)g_cand;
            float4* mem4 = (float4*)g_mem;
            const int total = ROWS * 75;
            for (int idx = blockIdx.x*NTHREADS + tid; idx < total;
                 idx += nblk*NTHREADS) {
                int r  = idx / 75;
                int jq = idx - r*75;
                int b  = r / MCELLS;
                float owv = g_ow[r], iv = g_indv[r];
                float coef = 1.f - owv - iv;
                float4 cd = cand4[idx];
                float4 h  = hb4[b*75 + jq];
                float4 mo = mem4[idx];
                float4 res;
                res.x = owv*h.x + coef*mo.x + iv*cd.x;
                res.y = owv*h.y + coef*mo.y + iv*cd.y;
                res.z = owv*h.z + coef*mo.z + iv*cd.z;
                res.w = owv*h.w + coef*mo.w + iv*cd.w;
                mem4[idx] = res;
            }
        }
        grid_bar(target, nblk);
    }
}

extern "C" void kernel_launch(void* const* d_in, const int* in_sizes, int n_in,
                              void* d_out, int out_size) {
    const float* hs   = (const float*)d_in[0];
    const float* mask = (const float*)d_in[1];
    const float* We1  = (const float*)d_in[2];
    const float* be1  = (const float*)d_in[3];
    const float* We2  = (const float*)d_in[4];
    const float* be2  = (const float*)d_in[5];
    const float* Ws1  = (const float*)d_in[6];
    const float* bs1  = (const float*)d_in[7];
    const float* Ws2  = (const float*)d_in[8];
    const float* bs2  = (const float*)d_in[9];
    const float* Wu   = (const float*)d_in[10];
    const float* bu   = (const float*)d_in[11];
    float* out = (float*)d_out;

    int smcount = 148;
    cudaDeviceGetAttribute(&smcount, cudaDevAttrMultiProcessorCount, 0);
    int nblk = 2 * smcount;

    void *pmem, *pusg, *pcnt, *pjob;
    cudaGetSymbolAddress(&pmem, g_mem);
    cudaGetSymbolAddress(&pusg, g_usage);
    cudaGetSymbolAddress(&pcnt, g_count);
    cudaGetSymbolAddress(&pjob, g_jobctr);
    cudaMemsetAsync(pmem, 0, sizeof(float)*(size_t)RH);
    cudaMemsetAsync(pusg, 0, sizeof(float)*(size_t)ROWS);
    cudaMemsetAsync(pcnt, 0, sizeof(unsigned));
    cudaMemsetAsync(pjob, 0, sizeof(unsigned)*T_STEPS);

    k_persist<<<nblk, NTHREADS>>>(hs, mask, We1, be1, We2, be2,
                                  Ws1, bs1, Ws2, bs2, Wu, bu, out, nblk);
}